// round 2
// baseline (speedup 1.0000x reference)
#include <cuda_runtime.h>
#include <math.h>

// Shapes (fixed by the problem)
#define BB 8
#define TT 512
#define DD 128
#define HH 8

typedef unsigned long long u64;

// Packed fp32x2 helpers (Blackwell sm_103a; ptxas never emits these from C++)
__device__ __forceinline__ u64 fadd2_(u64 a, u64 b) {
    u64 d; asm("add.rn.f32x2 %0, %1, %2;" : "=l"(d) : "l"(a), "l"(b)); return d;
}
__device__ __forceinline__ u64 ffma2_(u64 a, u64 b, u64 c) {
    u64 d; asm("fma.rn.f32x2 %0, %1, %2, %3;" : "=l"(d) : "l"(a), "l"(b), "l"(c)); return d;
}
__device__ __forceinline__ u64 pack2_(float x, float y) {
    u64 d; asm("mov.b64 %0, {%1, %2};" : "=l"(d) : "f"(x), "f"(y)); return d;
}
__device__ __forceinline__ float2 unpack2_(u64 v) {
    float2 f; asm("mov.b64 {%0, %1}, %2;" : "=f"(f.x), "=f"(f.y) : "l"(v)); return f;
}
#define ABSM 0x7fffffff7fffffffULL

// Scratch (allocation-free rule: __device__ globals)
__device__ float g_q[BB*HH*TT*DD];   // q[b][h][t][d]
__device__ float g_v[BB*HH*TT*DD];   // v[b][h][s][d]
__device__ float g_o[BB*HH*TT*DD];   // per-head attention output o[b][h][t][d]

// ---------------------------------------------------------------------------
// Kernel 1: QV projection.  y[bt][o] = sum_k x[bt][k] * Wqv[o][k] + Wqv[o][128]
// FFMA2-packed across k (two partial sums per accumulator).
// ---------------------------------------------------------------------------
__global__ __launch_bounds__(256) void qv_kernel(const float* __restrict__ x,
                                                 const float* __restrict__ w) {
    extern __shared__ float sm[];
    float* xs = sm;              // 64*128
    float* ws = sm + 64*128;     // 64*132 (padded)
    __shared__ float bsh[64];

    const int tid = threadIdx.x;
    const int tx  = tid & 15, ty = tid >> 4;
    const int m0 = blockIdx.y * 64;   // bt tile
    const int n0 = blockIdx.x * 64;   // o tile

    const float4* xg = (const float4*)(x + m0*DD);
    for (int i = tid; i < 64*32; i += 256)
        ((float4*)xs)[i] = xg[i];
    for (int i = tid; i < 64*128; i += 256) {
        int r = i >> 7, c = i & 127;
        ws[r*132 + c] = w[(size_t)(n0 + r)*129 + c];
    }
    if (tid < 64) bsh[tid] = w[(size_t)(n0 + tid)*129 + 128];
    __syncthreads();

    u64 acc2[4][4];
#pragma unroll
    for (int i = 0; i < 4; i++)
#pragma unroll
        for (int j = 0; j < 4; j++) acc2[i][j] = 0ULL;

#pragma unroll 4
    for (int k = 0; k < 128; k += 4) {
        ulonglong2 a[4], b[4];
#pragma unroll
        for (int i = 0; i < 4; i++) a[i] = *(const ulonglong2*)&xs[(ty*4 + i)*128 + k];
#pragma unroll
        for (int j = 0; j < 4; j++) b[j] = *(const ulonglong2*)&ws[(tx + 16*j)*132 + k];
#pragma unroll
        for (int i = 0; i < 4; i++)
#pragma unroll
            for (int j = 0; j < 4; j++) {
                acc2[i][j] = ffma2_(a[i].x, b[j].x, acc2[i][j]);
                acc2[i][j] = ffma2_(a[i].y, b[j].y, acc2[i][j]);
            }
    }

#pragma unroll
    for (int i = 0; i < 4; i++) {
        int m  = m0 + ty*4 + i;           // bt index
        int bi = m >> 9, t = m & 511;
#pragma unroll
        for (int j = 0; j < 4; j++) {
            int o  = n0 + tx + 16*j;
            int hh = o >> 8, c = o & 255;
            float2 f = unpack2_(acc2[i][j]);
            float val = f.x + f.y + bsh[tx + 16*j];
            float* dst = (c < 128) ? g_q : g_v;
            dst[(((size_t)(bi*HH + hh))*TT + t)*DD + (c & 127)] = val;
        }
    }
}

// ---------------------------------------------------------------------------
// Kernel 2: fused L1-distance attention per (b, h, 64 t-rows).
// Distance loop: k staged NEGATED -> diff = add.f32x2(q, -k); abs via 64-bit
// AND (alu pipe); accumulate via add.f32x2. 1 fma + 1 alu op per element.
// ---------------------------------------------------------------------------
__global__ __launch_bounds__(256) void attn_kernel(const float* __restrict__ x,
                                                   const float* __restrict__ wk,
                                                   const float* __restrict__ msk) {
    extern __shared__ float sm[];
    float* Ssh = sm;                 // 64*512
    float* qsh = sm + 64*512;        // 64*132
    float* ksh = qsh + 64*132;       // 64*132
    __shared__ float wksh[128];      // negated wk

    const int b  = blockIdx.z, h = blockIdx.y;
    const int t0 = blockIdx.x * 64;
    const int tid = threadIdx.x;
    const int tx  = tid & 15, ty = tid >> 4;

    if (tid < 128) wksh[tid] = -wk[h*DD + tid];

    // stage q tile
    const float4* qg = (const float4*)(g_q + (((size_t)(b*HH + h))*TT + t0)*DD);
    for (int i = tid; i < 64*32; i += 256) {
        int r = i >> 5, c4 = i & 31;
        float4 v = qg[i];
        *(float4*)&qsh[r*132 + c4*4] = v;
    }
    __syncthreads();

    const float NEG_ISQ = -0.08838834764831845f;  // -1/sqrt(128)

    // Phase 1: all score tiles (prefetch next x tile into registers)
    float4 kreg[8];
    {
        const float4* xg = (const float4*)(x + ((size_t)b*TT)*DD);
#pragma unroll
        for (int u = 0; u < 8; u++) kreg[u] = xg[tid + u*256];
    }

    for (int s0 = 0; s0 < TT; s0 += 64) {
        // store prefetched tile as NEGATED k
#pragma unroll
        for (int u = 0; u < 8; u++) {
            int i = tid + u*256;
            int r = i >> 5, c4 = i & 31;
            float4 v = kreg[u];
            v.x *= wksh[c4*4 + 0]; v.y *= wksh[c4*4 + 1];
            v.z *= wksh[c4*4 + 2]; v.w *= wksh[c4*4 + 3];
            *(float4*)&ksh[r*132 + c4*4] = v;
        }
        __syncthreads();

        if (s0 + 64 < TT) {
            const float4* xg = (const float4*)(x + ((size_t)b*TT + s0 + 64)*DD);
#pragma unroll
            for (int u = 0; u < 8; u++) kreg[u] = xg[tid + u*256];
        }

        u64 acc2[4][4];
#pragma unroll
        for (int i = 0; i < 4; i++)
#pragma unroll
            for (int j = 0; j < 4; j++) acc2[i][j] = 0ULL;

#pragma unroll 2
        for (int d = 0; d < 128; d += 4) {
            ulonglong2 qv[4], kv[4];
#pragma unroll
            for (int i = 0; i < 4; i++) qv[i] = *(const ulonglong2*)&qsh[(ty*4 + i)*132 + d];
#pragma unroll
            for (int j = 0; j < 4; j++) kv[j] = *(const ulonglong2*)&ksh[(tx + 16*j)*132 + d];
#pragma unroll
            for (int i = 0; i < 4; i++)
#pragma unroll
                for (int j = 0; j < 4; j++) {
                    u64 d0 = fadd2_(qv[i].x, kv[j].x) & ABSM;
                    u64 d1 = fadd2_(qv[i].y, kv[j].y) & ABSM;
                    acc2[i][j] = fadd2_(acc2[i][j], d0);
                    acc2[i][j] = fadd2_(acc2[i][j], d1);
                }
        }
#pragma unroll
        for (int i = 0; i < 4; i++)
#pragma unroll
            for (int j = 0; j < 4; j++) {
                float2 f = unpack2_(acc2[i][j]);
                Ssh[(ty*4 + i)*512 + s0 + tx + 16*j] = (f.x + f.y) * NEG_ISQ;
            }
        __syncthreads();
    }

    // Phase 2: row softmax + mask  (8 warps, 8 rows each)
    const int warp = tid >> 5, lane = tid & 31;
    for (int r = warp; r < 64; r += 8) {
        float* row = Ssh + r*512;
        float vals[16];
        float m = -1e30f;
#pragma unroll
        for (int i = 0; i < 16; i++) { vals[i] = row[lane + i*32]; m = fmaxf(m, vals[i]); }
#pragma unroll
        for (int o = 16; o > 0; o >>= 1) m = fmaxf(m, __shfl_xor_sync(0xffffffffu, m, o));
        float sum = 0.f;
#pragma unroll
        for (int i = 0; i < 16; i++) { vals[i] = __expf(vals[i] - m); sum += vals[i]; }
#pragma unroll
        for (int o = 16; o > 0; o >>= 1) sum += __shfl_xor_sync(0xffffffffu, sum, o);
        float inv = 1.f / sum;
        const float* mrow = msk + ((size_t)(h*TT + t0 + r))*TT;
#pragma unroll
        for (int i = 0; i < 16; i++)
            row[lane + i*32] = vals[i] * inv * mrow[lane + i*32];
    }
    __syncthreads();

    // Phase 3: O = P @ V  (FFMA2-packed across d; reuse qsh as v buffer)
    float* vsh = qsh;
    u64 oacc2[4][4];
#pragma unroll
    for (int i = 0; i < 4; i++)
#pragma unroll
        for (int j = 0; j < 4; j++) oacc2[i][j] = 0ULL;

    float4 vreg[8];
    {
        const float4* vg = (const float4*)(g_v + (((size_t)(b*HH + h))*TT)*DD);
#pragma unroll
        for (int u = 0; u < 8; u++) vreg[u] = vg[tid + u*256];
    }

    for (int s0 = 0; s0 < TT; s0 += 64) {
#pragma unroll
        for (int u = 0; u < 8; u++) {
            int i = tid + u*256;
            int r = i >> 5, c4 = i & 31;
            *(float4*)&vsh[r*132 + c4*4] = vreg[u];
        }
        __syncthreads();

        if (s0 + 64 < TT) {
            const float4* vg = (const float4*)(g_v + (((size_t)(b*HH + h))*TT + s0 + 64)*DD);
#pragma unroll
            for (int u = 0; u < 8; u++) vreg[u] = vg[tid + u*256];
        }

#pragma unroll 4
        for (int s = 0; s < 64; s++) {
            u64 pp[4];
#pragma unroll
            for (int i = 0; i < 4; i++) {
                float p = Ssh[(ty*4 + i)*512 + s0 + s];
                pp[i] = pack2_(p, p);
            }
            ulonglong2 v0 = *(const ulonglong2*)&vsh[s*132 + tx*4];
            ulonglong2 v1 = *(const ulonglong2*)&vsh[s*132 + 64 + tx*4];
#pragma unroll
            for (int i = 0; i < 4; i++) {
                oacc2[i][0] = ffma2_(pp[i], v0.x, oacc2[i][0]);
                oacc2[i][1] = ffma2_(pp[i], v0.y, oacc2[i][1]);
                oacc2[i][2] = ffma2_(pp[i], v1.x, oacc2[i][2]);
                oacc2[i][3] = ffma2_(pp[i], v1.y, oacc2[i][3]);
            }
        }
        __syncthreads();
    }

    float* og = g_o + (((size_t)(b*HH + h))*TT + t0)*DD;
#pragma unroll
    for (int i = 0; i < 4; i++) {
        int r = ty*4 + i;
        ulonglong2 w0, w1;
        w0.x = oacc2[i][0]; w0.y = oacc2[i][1];
        w1.x = oacc2[i][2]; w1.y = oacc2[i][3];
        *(ulonglong2*)&og[r*DD + tx*4]      = w0;
        *(ulonglong2*)&og[r*DD + 64 + tx*4] = w1;
    }
}

// ---------------------------------------------------------------------------
// Kernel 3: bo = sum_h o[b][h][t][:] ; yo = qgelu(bo+4.5)-4.5 ;
//           out = x + yo @ fanout^T + bias     (FFMA2-packed across i)
// ---------------------------------------------------------------------------
__global__ __launch_bounds__(256) void final_kernel(const float* __restrict__ x,
                                                    const float* __restrict__ fw,
                                                    float* __restrict__ out) {
    extern __shared__ float sm[];
    float* Wsh  = sm;            // 128*130 (row padded to 130 for u64 alignment)
    float* yosh = sm + 128*130;  // 16*128

    const int b = blockIdx.y, t0 = blockIdx.x * 16;
    const int tid = threadIdx.x;

    for (int i = tid; i < 128*129; i += 256) {
        int r = i / 129, c = i - r*129;
        Wsh[r*130 + c] = fw[i];
    }

    for (int i = tid; i < 16*128; i += 256) {
        int r = i >> 7, dd = i & 127;
        float bo = 0.f;
#pragma unroll
        for (int h = 0; h < HH; h++)
            bo += g_o[(((size_t)(b*HH + h))*TT + t0 + r)*DD + dd];
        float z  = bo + 4.5f;
        float sg = 1.f / (1.f + __expf(-1.702f * z));
        yosh[r*128 + dd] = z*sg - 4.5f;
    }
    __syncthreads();

    const int o = tid & 127, half = tid >> 7;
    u64 acc2[8];
#pragma unroll
    for (int rr = 0; rr < 8; rr++) acc2[rr] = 0ULL;

#pragma unroll 4
    for (int i = 0; i < 128; i += 2) {
        u64 w2 = *(const u64*)&Wsh[o*130 + i];
#pragma unroll
        for (int rr = 0; rr < 8; rr++)
            acc2[rr] = ffma2_(w2, *(const u64*)&yosh[(half*8 + rr)*128 + i], acc2[rr]);
    }
    float bias = Wsh[o*130 + 128];
#pragma unroll
    for (int rr = 0; rr < 8; rr++) {
        int t = t0 + half*8 + rr;
        size_t idx = ((size_t)b*TT + t)*DD + o;
        float2 f = unpack2_(acc2[rr]);
        out[idx] = x[idx] + f.x + f.y + bias;
    }
}

// ---------------------------------------------------------------------------
extern "C" void kernel_launch(void* const* d_in, const int* in_sizes, int n_in,
                              void* d_out, int out_size) {
    const float* x   = (const float*)d_in[0];
    const float* msk = (const float*)d_in[1];
    const float* wqv = (const float*)d_in[2];
    const float* wk  = (const float*)d_in[3];
    const float* fw  = (const float*)d_in[4];
    float* out = (float*)d_out;

    cudaFuncSetAttribute(qv_kernel,    cudaFuncAttributeMaxDynamicSharedMemorySize,
                         (64*128 + 64*132) * 4);
    cudaFuncSetAttribute(attn_kernel,  cudaFuncAttributeMaxDynamicSharedMemorySize,
                         (64*512 + 2*64*132) * 4);
    cudaFuncSetAttribute(final_kernel, cudaFuncAttributeMaxDynamicSharedMemorySize,
                         (128*130 + 16*128) * 4);

    qv_kernel<<<dim3(32, 64), 256, (64*128 + 64*132) * 4>>>(x, wqv);
    attn_kernel<<<dim3(TT/64, HH, BB), 256, (64*512 + 2*64*132) * 4>>>(x, wk, msk);
    final_kernel<<<dim3(TT/16, BB), 256, (128*130 + 16*128) * 4>>>(x, fw, out);
}